// round 6
// baseline (speedup 1.0000x reference)
#include <cuda_runtime.h>

#define NROW 4096
#define DDIM 64

// ---------------- device scratch (no allocations allowed) ----------------
static __device__ float        g_xx[(long long)NROW * NROW];   // 64 MB dist(x,x)
static __device__ float        g_yy[(long long)NROW * NROW];   // 64 MB dist(y,y)
static __device__ float        g_zz[(long long)NROW * NROW];   // 64 MB dist(x,y)
static __device__ float        g_norms[2][NROW];               // row norms of x, y
static __device__ float        g_rows[3][NROW];                // stage-A f32 row sums
static __device__ float        g_S[3];                         // stage-B f32 sums
static __device__ unsigned int g_h0[2048];
static __device__ unsigned int g_h1[2048];
static __device__ unsigned int g_h2[1024];
static __device__ unsigned int g_pfx0, g_pfx1, g_rank;
static __device__ float        g_par[5];   // s_k = (-1/median) * kernel_scales[k], f32

// device-side selector (NEVER pass __device__ symbols from host code!)
__device__ __forceinline__ float* mat_of(int slot) {
    return (slot == 0) ? g_xx : (slot == 1) ? g_yy : g_zz;
}

// ---------------- helpers ----------------
// Cephes-style minimax expf (~1 ulp, zero-mean error). Flag-proof: FMA only.
__device__ __forceinline__ float my_exp(float x) {
    x = fmaxf(x, -87.0f);
    float z = floorf(fmaf(x, 1.44269504088896341f, 0.5f));
    float r = fmaf(z, -0.693359375f, x);
    r = fmaf(z, 2.12194440e-4f, r);
    int n = (int)z;
    float p = 1.9875691500e-4f;
    p = fmaf(p, r, 1.3981999507e-3f);
    p = fmaf(p, r, 8.3334519073e-3f);
    p = fmaf(p, r, 4.1665795894e-2f);
    p = fmaf(p, r, 1.6666665459e-1f);
    p = fmaf(p, r, 5.0000001201e-1f);
    float res = fmaf(p, r * r, r) + 1.0f;
    return res * __int_as_float((n + 127) << 23);
}

// per-element multi-kernel MEAN in f32: ((((e0+e1)+e2)+e3)+e4) / 5.0f
__device__ __forceinline__ float kmean5(float d, float s0, float s1, float s2,
                                        float s3, float s4) {
    float s = my_exp(d * s0);
    s = s + my_exp(d * s1);
    s = s + my_exp(d * s2);
    s = s + my_exp(d * s3);
    s = s + my_exp(d * s4);
    return s / 5.0f;
}

// monotone key transform for float radix select
__device__ __forceinline__ unsigned int fkey(float f) {
    unsigned int b = __float_as_uint(f);
    return b ^ ((b & 0x80000000u) ? 0xffffffffu : 0x80000000u);
}

// warp-aggregated shared histogram add
__device__ __forceinline__ void hadd(unsigned int* sh, unsigned int bin) {
    unsigned int m = __match_any_sync(0xffffffffu, bin);
    if ((int)(threadIdx.x & 31u) == (int)(__ffs(m) - 1))
        atomicAdd(&sh[bin], (unsigned int)__popc(m));
}

// ---------------- kernels ----------------
__global__ void k_init() {
    int t = threadIdx.x;
    for (int i = t; i < 2048; i += 256) { g_h0[i] = 0u; g_h1[i] = 0u; }
    for (int i = t; i < 1024; i += 256) g_h2[i] = 0u;
    if (t == 0) {
        g_rank = 8388607u;  // (N*N - 1) / 2 : lower-median rank (0-indexed)
        g_pfx0 = 0u; g_pfx1 = 0u;
    }
}

__global__ void k_rownorm(const float* __restrict__ a, int which) {
    int row  = blockIdx.x * 8 + (threadIdx.x >> 5);
    int lane = threadIdx.x & 31;
    float v0 = a[row * DDIM + lane];
    float v1 = a[row * DDIM + 32 + lane];
    float s  = v0 * v0 + v1 * v1;
#pragma unroll
    for (int o = 16; o > 0; o >>= 1) s += __shfl_down_sync(0xffffffffu, s, o);
    if (lane == 0) g_norms[which][row] = s;
}

// Tiled distance kernel: 64x64 tile, 256 threads, 4x4 per thread, K = 64.
// Stores dist to mat_of(outsel).
__global__ void __launch_bounds__(256) k_tile(const float* __restrict__ A,
                                              const float* __restrict__ B,
                                              int anw, int bnw, int outsel) {
    __shared__ float As[64][69];
    __shared__ float Bs[64][69];
    float* OUT = mat_of(outsel);
    const int bm  = blockIdx.y * 64;
    const int bc  = blockIdx.x * 64;
    const int tid = threadIdx.x;

#pragma unroll
    for (int t = tid; t < 4096; t += 256) {
        int r = t >> 6, c = t & 63;
        As[r][c] = A[(long long)(bm + r) * DDIM + c];
        Bs[r][c] = B[(long long)(bc + r) * DDIM + c];
    }
    __syncthreads();

    const int tx = tid & 15, ty = tid >> 4;
    float acc[4][4];
#pragma unroll
    for (int m = 0; m < 4; m++)
#pragma unroll
        for (int n = 0; n < 4; n++) acc[m][n] = 0.0f;

#pragma unroll 8
    for (int k = 0; k < 64; k++) {
        float av[4], bv[4];
#pragma unroll
        for (int m = 0; m < 4; m++) av[m] = As[ty * 4 + m][k];
#pragma unroll
        for (int n = 0; n < 4; n++) bv[n] = Bs[tx * 4 + n][k];
#pragma unroll
        for (int m = 0; m < 4; m++)
#pragma unroll
            for (int n = 0; n < 4; n++)
                acc[m][n] = fmaf(av[m], bv[n], acc[m][n]);
    }

    const float* an = g_norms[anw];
    const float* bn = g_norms[bnw];
#pragma unroll
    for (int m = 0; m < 4; m++) {
        int r = bm + ty * 4 + m;
        float base = an[r];
        float4 o;
        o.x = fmaf(-2.0f, acc[m][0], base + bn[bc + tx * 4 + 0]);
        o.y = fmaf(-2.0f, acc[m][1], base + bn[bc + tx * 4 + 1]);
        o.z = fmaf(-2.0f, acc[m][2], base + bn[bc + tx * 4 + 2]);
        o.w = fmaf(-2.0f, acc[m][3], base + bn[bc + tx * 4 + 3]);
        *reinterpret_cast<float4*>(&OUT[(long long)r * NROW + bc + tx * 4]) = o;
    }
}

// ---- 3-pass radix select for exact lower median over g_xx ----
__global__ void k_hist0() {
    __shared__ unsigned int sh[2048];
    for (int i = threadIdx.x; i < 2048; i += 256) sh[i] = 0u;
    __syncthreads();
    const float4* p = reinterpret_cast<const float4*>(g_xx);
    unsigned int i = blockIdx.x * 256u + threadIdx.x;
    const unsigned int stride = 1024u * 256u;
#pragma unroll 2
    for (int it = 0; it < 16; it++, i += stride) {
        float4 v = p[i];
        hadd(sh, fkey(v.x) >> 21);
        hadd(sh, fkey(v.y) >> 21);
        hadd(sh, fkey(v.z) >> 21);
        hadd(sh, fkey(v.w) >> 21);
    }
    __syncthreads();
    for (int i2 = threadIdx.x; i2 < 2048; i2 += 256) {
        unsigned int v = sh[i2];
        if (v) atomicAdd(&g_h0[i2], v);
    }
}

__global__ void k_hist1() {
    __shared__ unsigned int sh[2048];
    for (int i = threadIdx.x; i < 2048; i += 256) sh[i] = 0u;
    __syncthreads();
    const unsigned int pfx = g_pfx0;
    const float4* p = reinterpret_cast<const float4*>(g_xx);
    unsigned int i = blockIdx.x * 256u + threadIdx.x;
    const unsigned int stride = 1024u * 256u;
    for (int it = 0; it < 16; it++, i += stride) {
        float4 v = p[i];
        unsigned int k;
        k = fkey(v.x); if ((k >> 21) == pfx) atomicAdd(&sh[(k >> 10) & 2047u], 1u);
        k = fkey(v.y); if ((k >> 21) == pfx) atomicAdd(&sh[(k >> 10) & 2047u], 1u);
        k = fkey(v.z); if ((k >> 21) == pfx) atomicAdd(&sh[(k >> 10) & 2047u], 1u);
        k = fkey(v.w); if ((k >> 21) == pfx) atomicAdd(&sh[(k >> 10) & 2047u], 1u);
    }
    __syncthreads();
    for (int i2 = threadIdx.x; i2 < 2048; i2 += 256) {
        unsigned int v = sh[i2];
        if (v) atomicAdd(&g_h1[i2], v);
    }
}

__global__ void k_hist2() {
    __shared__ unsigned int sh[1024];
    for (int i = threadIdx.x; i < 1024; i += 256) sh[i] = 0u;
    __syncthreads();
    const unsigned int pfx = g_pfx1;
    const float4* p = reinterpret_cast<const float4*>(g_xx);
    unsigned int i = blockIdx.x * 256u + threadIdx.x;
    const unsigned int stride = 1024u * 256u;
    for (int it = 0; it < 16; it++, i += stride) {
        float4 v = p[i];
        unsigned int k;
        k = fkey(v.x); if ((k >> 10) == pfx) atomicAdd(&sh[k & 1023u], 1u);
        k = fkey(v.y); if ((k >> 10) == pfx) atomicAdd(&sh[k & 1023u], 1u);
        k = fkey(v.z); if ((k >> 10) == pfx) atomicAdd(&sh[k & 1023u], 1u);
        k = fkey(v.w); if ((k >> 10) == pfx) atomicAdd(&sh[k & 1023u], 1u);
    }
    __syncthreads();
    for (int i2 = threadIdx.x; i2 < 1024; i2 += 256) {
        unsigned int v = sh[i2];
        if (v) atomicAdd(&g_h2[i2], v);
    }
}

__global__ void k_select(int pass, const float* __restrict__ ks) {
    __shared__ unsigned int sh[2048];
    __shared__ unsigned int part[64];
    const unsigned int* hist = (pass == 0) ? g_h0 : (pass == 1) ? g_h1 : g_h2;
    const int nbins = (pass == 2) ? 1024 : 2048;
    const int per   = nbins / 64;
    const int tid   = threadIdx.x;  // 64 threads
    unsigned int s = 0;
    for (int i = 0; i < per; i++) {
        unsigned int v = hist[tid * per + i];
        sh[tid * per + i] = v;
        s += v;
    }
    part[tid] = s;
    __syncthreads();
    if (tid == 0) {
        unsigned int rank = g_rank, cum = 0;
        int seg = 0;
        while (seg < 63 && cum + part[seg] <= rank) { cum += part[seg]; seg++; }
        int b = seg * per;
        while (cum + sh[b] <= rank) { cum += sh[b]; b++; }
        g_rank = rank - cum;
        if (pass == 0) {
            g_pfx0 = (unsigned int)b;
        } else if (pass == 1) {
            g_pfx1 = (g_pfx0 << 11) | (unsigned int)b;
        } else {
            unsigned int key  = (g_pfx1 << 10) | (unsigned int)b;
            unsigned int bits = (key & 0x80000000u) ? (key ^ 0x80000000u) : ~key;
            float med  = __uint_as_float(bits);
            float base = -1.0f / med;           // f32 divide, like reference
            g_par[0] = base * ks[0];
            g_par[1] = base * ks[1];
            g_par[2] = base * ks[2];
            g_par[3] = base * ks[3];
            g_par[4] = base * ks[4];
        }
    }
}

// Stage-A: replica of XLA:GPU row reduction for row length 4096:
// 256 threads, vector size 2 (thread t owns elements 2t, 2t+1 per step),
// 8 strided iterations (stride 512 elements), float2 accumulator,
// acc.x + acc.y, warp shfl-down tree, 8 warp partials -> warp-0 tree.
// One block per row. diagskip: diagonal element contributes literal 0.0f.
__global__ void __launch_bounds__(256) k_rowreduce(int slot, int diagskip) {
    __shared__ float ws[8];
    const int r = blockIdx.x;
    const int t = threadIdx.x;
    float s0 = g_par[0], s1 = g_par[1], s2 = g_par[2], s3 = g_par[3], s4 = g_par[4];
    const float* M = mat_of(slot);
    const float2* p = reinterpret_cast<const float2*>(M + (long long)r * NROW);

    float ax = 0.0f, ay = 0.0f;
#pragma unroll
    for (int i = 0; i < 8; i++) {
        float2 v = p[i * 256 + t];
        int c = (i * 256 + t) * 2;
        float kx = (diagskip && c == r)     ? 0.0f : kmean5(v.x, s0, s1, s2, s3, s4);
        float ky = (diagskip && c + 1 == r) ? 0.0f : kmean5(v.y, s0, s1, s2, s3, s4);
        ax += kx;
        ay += ky;
    }
    float v = ax + ay;
#pragma unroll
    for (int o = 16; o > 0; o >>= 1) v += __shfl_down_sync(0xffffffffu, v, o);
    if ((t & 31) == 0) ws[t >> 5] = v;
    __syncthreads();
    if (t < 32) {
        float w = (t < 8) ? ws[t] : 0.0f;
#pragma unroll
        for (int o = 16; o > 0; o >>= 1) w += __shfl_down_sync(0xffffffffu, w, o);
        if (t == 0) g_rows[slot][r] = w;
    }
}

// Stage-B: identical layout applied to the 4096 f32 row sums -> scalar f32.
__global__ void __launch_bounds__(256) k_stageB(int slot) {
    __shared__ float ws[8];
    const int t = threadIdx.x;
    const float2* p = reinterpret_cast<const float2*>(g_rows[slot]);
    float ax = 0.0f, ay = 0.0f;
#pragma unroll
    for (int i = 0; i < 8; i++) {
        float2 v = p[i * 256 + t];
        ax += v.x;
        ay += v.y;
    }
    float v = ax + ay;
#pragma unroll
    for (int o = 16; o > 0; o >>= 1) v += __shfl_down_sync(0xffffffffu, v, o);
    if ((t & 31) == 0) ws[t >> 5] = v;
    __syncthreads();
    if (t < 32) {
        float w = (t < 8) ? ws[t] : 0.0f;
#pragma unroll
        for (int o = 16; o > 0; o >>= 1) w += __shfl_down_sync(0xffffffffu, w, o);
        if (t == 0) g_S[slot] = w;
    }
}

// Final combine replicating the reference's f32 arithmetic.
__global__ void k_fin(float* out) {
    float S1 = g_S[0], S2 = g_S[1], S3 = g_S[2];
    float od = (float)(1.0 / 16773120.0);        // 1/(4096*4095) rounded to f32
    float t1 = od * S1;
    float t2 = od * S2;
    float m3 = S3 * (1.0f / 16777216.0f);        // exact power-of-two scale
    float t3 = 2.0f * m3;                        // exact
    out[0] = (t1 + t2) - t3;
}

// ---------------- entry ----------------
extern "C" void kernel_launch(void* const* d_in, const int* in_sizes, int n_in,
                              void* d_out, int out_size) {
    (void)in_sizes; (void)n_in; (void)out_size;
    const float* x  = (const float*)d_in[0];
    const float* y  = (const float*)d_in[1];
    const float* ks = (const float*)d_in[2];

    k_init<<<1, 256>>>();
    k_rownorm<<<512, 256>>>(x, 0);
    k_rownorm<<<512, 256>>>(y, 1);

    dim3 tg(64, 64);
    k_tile<<<tg, 256>>>(x, x, 0, 0, 0);   // -> g_xx
    k_tile<<<tg, 256>>>(y, y, 1, 1, 1);   // -> g_yy
    k_tile<<<tg, 256>>>(x, y, 0, 1, 2);   // -> g_zz

    k_hist0<<<1024, 256>>>();
    k_select<<<1, 64>>>(0, ks);
    k_hist1<<<1024, 256>>>();
    k_select<<<1, 64>>>(1, ks);
    k_hist2<<<1024, 256>>>();
    k_select<<<1, 64>>>(2, ks);              // -> median, scale params

    k_rowreduce<<<4096, 256>>>(0, 1);        // Sxx rows (diag -> 0)
    k_rowreduce<<<4096, 256>>>(1, 1);        // Syy rows (diag -> 0)
    k_rowreduce<<<4096, 256>>>(2, 0);        // Szz rows (full)

    k_stageB<<<1, 256>>>(0);
    k_stageB<<<1, 256>>>(1);
    k_stageB<<<1, 256>>>(2);

    k_fin<<<1, 1>>>((float*)d_out);
}

// round 7
// speedup vs baseline: 1.4991x; 1.4991x over previous
#include <cuda_runtime.h>

#define NROW 4096
#define DDIM 64

// ---------------- device scratch (no allocations allowed) ----------------
static __device__ float        g_xx[(long long)NROW * NROW];   // 64 MB dist(x,x)
static __device__ float        g_yy[(long long)NROW * NROW];   // 64 MB dist(y,y)
static __device__ float        g_zz[(long long)NROW * NROW];   // 64 MB dist(x,y)
static __device__ float        g_norms[2][NROW];               // row norms of x, y
static __device__ float        g_rows[3][NROW];                // stage-A f32 row sums
static __device__ float        g_S[3];                         // stage-B f32 sums
static __device__ unsigned int g_h0[2048];
static __device__ unsigned int g_h1[2048];
static __device__ unsigned int g_h2[1024];
static __device__ unsigned int g_pfx0, g_pfx1, g_rank;
static __device__ float        g_par[8];   // [0..4]=s_k, [5]=fast-chain flag

// device-side selector (never pass __device__ symbols from host code)
__device__ __forceinline__ float* mat_of(int slot) {
    return (slot == 0) ? g_xx : (slot == 1) ? g_yy : g_zz;
}

// ---------------- helpers ----------------
// Cephes-style minimax expf (~1 ulp, zero-mean error). Flag-proof: FMA only.
__device__ __forceinline__ float my_exp(float x) {
    x = fmaxf(x, -87.0f);
    float z = floorf(fmaf(x, 1.44269504088896341f, 0.5f));
    float r = fmaf(z, -0.693359375f, x);
    r = fmaf(z, 2.12194440e-4f, r);
    int n = (int)z;
    float p = 1.9875691500e-4f;
    p = fmaf(p, r, 1.3981999507e-3f);
    p = fmaf(p, r, 8.3334519073e-3f);
    p = fmaf(p, r, 4.1665795894e-2f);
    p = fmaf(p, r, 1.6666665459e-1f);
    p = fmaf(p, r, 5.0000001201e-1f);
    float res = fmaf(p, r * r, r) + 1.0f;
    return res * __int_as_float((n + 127) << 23);
}

// exact-replica 5-exp kernel mean: ((((e0+e1)+e2)+e3)+e4) / 5.0f
__device__ __forceinline__ float kmean5(float d, float s0, float s1, float s2,
                                        float s3, float s4) {
    float s = my_exp(d * s0);
    s = s + my_exp(d * s1);
    s = s + my_exp(d * s2);
    s = s + my_exp(d * s3);
    s = s + my_exp(d * s4);
    return s / 5.0f;
}

// fast chain (valid when s_{k+1} == 2*s_k exactly): 2 exps + 3 muls.
// arg scaling by 2/4/8/16 is bitwise exact, so args match the 5-exp path.
__device__ __forceinline__ float kmean5f(float d, float s0) {
    float v  = d * s0;
    float e0 = my_exp(v);
    float e2 = my_exp(4.0f * v);
    float e1 = e0 * e0;      // exp(2v)
    float e3 = e2 * e2;      // exp(8v)
    float e4 = e3 * e3;      // exp(16v)
    float s = e0 + e1;
    s = s + e2;
    s = s + e3;
    s = s + e4;
    return s / 5.0f;
}

// monotone key transform for float radix select
__device__ __forceinline__ unsigned int fkey(float f) {
    unsigned int b = __float_as_uint(f);
    return b ^ ((b & 0x80000000u) ? 0xffffffffu : 0x80000000u);
}

// warp-aggregated shared histogram add
__device__ __forceinline__ void hadd(unsigned int* sh, unsigned int bin) {
    unsigned int m = __match_any_sync(0xffffffffu, bin);
    if ((int)(threadIdx.x & 31u) == (int)(__ffs(m) - 1))
        atomicAdd(&sh[bin], (unsigned int)__popc(m));
}

// ---------------- kernels ----------------
__global__ void k_init() {
    int t = threadIdx.x;
    for (int i = t; i < 2048; i += 256) { g_h0[i] = 0u; g_h1[i] = 0u; }
    for (int i = t; i < 1024; i += 256) g_h2[i] = 0u;
    if (t == 0) {
        g_rank = 8388607u;  // (N*N - 1) / 2 : lower-median rank
        g_pfx0 = 0u; g_pfx1 = 0u;
    }
}

__global__ void k_rownorm(const float* __restrict__ a, int which) {
    int row  = blockIdx.x * 8 + (threadIdx.x >> 5);
    int lane = threadIdx.x & 31;
    float v0 = a[row * DDIM + lane];
    float v1 = a[row * DDIM + 32 + lane];
    float s  = v0 * v0 + v1 * v1;
#pragma unroll
    for (int o = 16; o > 0; o >>= 1) s += __shfl_down_sync(0xffffffffu, s, o);
    if (lane == 0) g_norms[which][row] = s;
}

// 128x128 tile, 256 threads, 8x8 per thread, K=64, grid.z selects matrix.
// Thread mapping: m = ty + 16*i, n = 2*tx + 32*h + w (float2 stores,
// conflict-free LDS). Per-(r,c) accumulation order (k = 0..63, fmaf)
// is IDENTICAL to the previous kernel -> bit-exact distances.
__global__ void __launch_bounds__(256, 2) k_tile128(const float* __restrict__ x,
                                                    const float* __restrict__ y) {
    extern __shared__ float sm[];
    float* As = sm;             // [128][69]
    float* Bs = sm + 128 * 69;  // [128][69]

    const int z = blockIdx.z;
    const float* A = (z == 1) ? y : x;
    const float* B = (z == 0) ? x : y;
    const int anw = (z == 1) ? 1 : 0;
    const int bnw = (z == 0) ? 0 : 1;
    float* OUT = mat_of(z);

    const int bm  = blockIdx.y * 128;
    const int bc  = blockIdx.x * 128;
    const int tid = threadIdx.x;

    const float4* Ag = reinterpret_cast<const float4*>(A + (long long)bm * DDIM);
    const float4* Bg = reinterpret_cast<const float4*>(B + (long long)bc * DDIM);
#pragma unroll
    for (int i = tid; i < 2048; i += 256) {
        int row = i >> 4, f4 = i & 15;
        float4 va = Ag[row * 16 + f4];
        float4 vb = Bg[row * 16 + f4];
        int c4 = f4 * 4;
        As[row * 69 + c4 + 0] = va.x; As[row * 69 + c4 + 1] = va.y;
        As[row * 69 + c4 + 2] = va.z; As[row * 69 + c4 + 3] = va.w;
        Bs[row * 69 + c4 + 0] = vb.x; Bs[row * 69 + c4 + 1] = vb.y;
        Bs[row * 69 + c4 + 2] = vb.z; Bs[row * 69 + c4 + 3] = vb.w;
    }
    __syncthreads();

    const int tx = tid & 15, ty = tid >> 4;
    float acc[8][8];
#pragma unroll
    for (int i = 0; i < 8; i++)
#pragma unroll
        for (int j = 0; j < 8; j++) acc[i][j] = 0.0f;

#pragma unroll 4
    for (int k = 0; k < 64; k++) {
        float av[8], bv[8];
#pragma unroll
        for (int i = 0; i < 8; i++) av[i] = As[(ty + 16 * i) * 69 + k];
#pragma unroll
        for (int j = 0; j < 8; j++) {
            int n = 2 * tx + 32 * (j >> 1) + (j & 1);
            bv[j] = Bs[n * 69 + k];
        }
#pragma unroll
        for (int i = 0; i < 8; i++)
#pragma unroll
            for (int j = 0; j < 8; j++)
                acc[i][j] = fmaf(av[i], bv[j], acc[i][j]);
    }

    const float* an = g_norms[anw];
    const float* bn = g_norms[bnw];
#pragma unroll
    for (int i = 0; i < 8; i++) {
        int r = bm + ty + 16 * i;
        float base = an[r];
#pragma unroll
        for (int h = 0; h < 4; h++) {
            int c = bc + 2 * tx + 32 * h;
            float2 o;
            o.x = fmaf(-2.0f, acc[i][2 * h + 0], base + bn[c + 0]);
            o.y = fmaf(-2.0f, acc[i][2 * h + 1], base + bn[c + 1]);
            *reinterpret_cast<float2*>(&OUT[(long long)r * NROW + c]) = o;
        }
    }
}

// ---- 3-pass radix select for exact lower median over g_xx ----
__global__ void k_hist0() {
    __shared__ unsigned int sh[2048];
    for (int i = threadIdx.x; i < 2048; i += 256) sh[i] = 0u;
    __syncthreads();
    const float4* p = reinterpret_cast<const float4*>(g_xx);
    unsigned int i = blockIdx.x * 256u + threadIdx.x;
    const unsigned int stride = 1024u * 256u;
#pragma unroll 2
    for (int it = 0; it < 16; it++, i += stride) {
        float4 v = p[i];
        hadd(sh, fkey(v.x) >> 21);
        hadd(sh, fkey(v.y) >> 21);
        hadd(sh, fkey(v.z) >> 21);
        hadd(sh, fkey(v.w) >> 21);
    }
    __syncthreads();
    for (int i2 = threadIdx.x; i2 < 2048; i2 += 256) {
        unsigned int v = sh[i2];
        if (v) atomicAdd(&g_h0[i2], v);
    }
}

__global__ void k_hist1() {
    __shared__ unsigned int sh[2048];
    for (int i = threadIdx.x; i < 2048; i += 256) sh[i] = 0u;
    __syncthreads();
    const unsigned int pfx = g_pfx0;
    const float4* p = reinterpret_cast<const float4*>(g_xx);
    unsigned int i = blockIdx.x * 256u + threadIdx.x;
    const unsigned int stride = 1024u * 256u;
    for (int it = 0; it < 16; it++, i += stride) {
        float4 v = p[i];
        unsigned int k;
        k = fkey(v.x); if ((k >> 21) == pfx) atomicAdd(&sh[(k >> 10) & 2047u], 1u);
        k = fkey(v.y); if ((k >> 21) == pfx) atomicAdd(&sh[(k >> 10) & 2047u], 1u);
        k = fkey(v.z); if ((k >> 21) == pfx) atomicAdd(&sh[(k >> 10) & 2047u], 1u);
        k = fkey(v.w); if ((k >> 21) == pfx) atomicAdd(&sh[(k >> 10) & 2047u], 1u);
    }
    __syncthreads();
    for (int i2 = threadIdx.x; i2 < 2048; i2 += 256) {
        unsigned int v = sh[i2];
        if (v) atomicAdd(&g_h1[i2], v);
    }
}

__global__ void k_hist2() {
    __shared__ unsigned int sh[1024];
    for (int i = threadIdx.x; i < 1024; i += 256) sh[i] = 0u;
    __syncthreads();
    const unsigned int pfx = g_pfx1;
    const float4* p = reinterpret_cast<const float4*>(g_xx);
    unsigned int i = blockIdx.x * 256u + threadIdx.x;
    const unsigned int stride = 1024u * 256u;
    for (int it = 0; it < 16; it++, i += stride) {
        float4 v = p[i];
        unsigned int k;
        k = fkey(v.x); if ((k >> 10) == pfx) atomicAdd(&sh[k & 1023u], 1u);
        k = fkey(v.y); if ((k >> 10) == pfx) atomicAdd(&sh[k & 1023u], 1u);
        k = fkey(v.z); if ((k >> 10) == pfx) atomicAdd(&sh[k & 1023u], 1u);
        k = fkey(v.w); if ((k >> 10) == pfx) atomicAdd(&sh[k & 1023u], 1u);
    }
    __syncthreads();
    for (int i2 = threadIdx.x; i2 < 1024; i2 += 256) {
        unsigned int v = sh[i2];
        if (v) atomicAdd(&g_h2[i2], v);
    }
}

__global__ void k_select(int pass, const float* __restrict__ ks) {
    __shared__ unsigned int sh[2048];
    __shared__ unsigned int part[64];
    const unsigned int* hist = (pass == 0) ? g_h0 : (pass == 1) ? g_h1 : g_h2;
    const int nbins = (pass == 2) ? 1024 : 2048;
    const int per   = nbins / 64;
    const int tid   = threadIdx.x;  // 64 threads
    unsigned int s = 0;
    for (int i = 0; i < per; i++) {
        unsigned int v = hist[tid * per + i];
        sh[tid * per + i] = v;
        s += v;
    }
    part[tid] = s;
    __syncthreads();
    if (tid == 0) {
        unsigned int rank = g_rank, cum = 0;
        int seg = 0;
        while (seg < 63 && cum + part[seg] <= rank) { cum += part[seg]; seg++; }
        int b = seg * per;
        while (cum + sh[b] <= rank) { cum += sh[b]; b++; }
        g_rank = rank - cum;
        if (pass == 0) {
            g_pfx0 = (unsigned int)b;
        } else if (pass == 1) {
            g_pfx1 = (g_pfx0 << 11) | (unsigned int)b;
        } else {
            unsigned int key  = (g_pfx1 << 10) | (unsigned int)b;
            unsigned int bits = (key & 0x80000000u) ? (key ^ 0x80000000u) : ~key;
            float med  = __uint_as_float(bits);
            float base = -1.0f / med;
            float p0 = base * ks[0], p1 = base * ks[1], p2 = base * ks[2];
            float p3 = base * ks[3], p4 = base * ks[4];
            g_par[0] = p0; g_par[1] = p1; g_par[2] = p2; g_par[3] = p3; g_par[4] = p4;
            bool fast = (p1 == 2.0f * p0) && (p2 == 2.0f * p1) &&
                        (p3 == 2.0f * p2) && (p4 == 2.0f * p3);
            g_par[5] = fast ? 1.0f : 0.0f;
        }
    }
}

// Stage-A XLA row-reduction replica (bit-exact shape). grid=(4096, 3).
__global__ void __launch_bounds__(256) k_rowreduce() {
    __shared__ float ws[8];
    const int r    = blockIdx.x;
    const int slot = blockIdx.y;
    const int diagskip = (slot != 2) ? 1 : 0;
    const int t = threadIdx.x;
    float s0 = g_par[0], s1 = g_par[1], s2 = g_par[2], s3 = g_par[3], s4 = g_par[4];
    const bool fast = g_par[5] > 0.5f;
    const float* M = mat_of(slot);
    const float2* p = reinterpret_cast<const float2*>(M + (long long)r * NROW);

    float ax = 0.0f, ay = 0.0f;
    if (fast) {
#pragma unroll
        for (int i = 0; i < 8; i++) {
            float2 v = p[i * 256 + t];
            int c = (i * 256 + t) * 2;
            float kx = kmean5f(v.x, s0);
            float ky = kmean5f(v.y, s0);
            if (diagskip && c == r)     kx = 0.0f;
            if (diagskip && c + 1 == r) ky = 0.0f;
            ax += kx;
            ay += ky;
        }
    } else {
#pragma unroll
        for (int i = 0; i < 8; i++) {
            float2 v = p[i * 256 + t];
            int c = (i * 256 + t) * 2;
            float kx = (diagskip && c == r)     ? 0.0f : kmean5(v.x, s0, s1, s2, s3, s4);
            float ky = (diagskip && c + 1 == r) ? 0.0f : kmean5(v.y, s0, s1, s2, s3, s4);
            ax += kx;
            ay += ky;
        }
    }
    float v = ax + ay;
#pragma unroll
    for (int o = 16; o > 0; o >>= 1) v += __shfl_down_sync(0xffffffffu, v, o);
    if ((t & 31) == 0) ws[t >> 5] = v;
    __syncthreads();
    if (t < 32) {
        float w = (t < 8) ? ws[t] : 0.0f;
#pragma unroll
        for (int o = 16; o > 0; o >>= 1) w += __shfl_down_sync(0xffffffffu, w, o);
        if (t == 0) g_rows[slot][r] = w;
    }
}

// Stage-B: same reduce shape over the 4096 f32 row sums. grid=3.
__global__ void __launch_bounds__(256) k_stageB() {
    __shared__ float ws[8];
    const int slot = blockIdx.x;
    const int t = threadIdx.x;
    const float2* p = reinterpret_cast<const float2*>(g_rows[slot]);
    float ax = 0.0f, ay = 0.0f;
#pragma unroll
    for (int i = 0; i < 8; i++) {
        float2 v = p[i * 256 + t];
        ax += v.x;
        ay += v.y;
    }
    float v = ax + ay;
#pragma unroll
    for (int o = 16; o > 0; o >>= 1) v += __shfl_down_sync(0xffffffffu, v, o);
    if ((t & 31) == 0) ws[t >> 5] = v;
    __syncthreads();
    if (t < 32) {
        float w = (t < 8) ? ws[t] : 0.0f;
#pragma unroll
        for (int o = 16; o > 0; o >>= 1) w += __shfl_down_sync(0xffffffffu, w, o);
        if (t == 0) g_S[slot] = w;
    }
}

// Final combine replicating the reference's f32 arithmetic.
__global__ void k_fin(float* out) {
    float S1 = g_S[0], S2 = g_S[1], S3 = g_S[2];
    float od = (float)(1.0 / 16773120.0);        // 1/(4096*4095) in f32
    float t1 = od * S1;
    float t2 = od * S2;
    float m3 = S3 * (1.0f / 16777216.0f);        // exact power-of-two scale
    float t3 = 2.0f * m3;                        // exact
    out[0] = (t1 + t2) - t3;
}

// ---------------- entry ----------------
extern "C" void kernel_launch(void* const* d_in, const int* in_sizes, int n_in,
                              void* d_out, int out_size) {
    (void)in_sizes; (void)n_in; (void)out_size;
    const float* x  = (const float*)d_in[0];
    const float* y  = (const float*)d_in[1];
    const float* ks = (const float*)d_in[2];

    const int TILE_SMEM = 2 * 128 * 69 * (int)sizeof(float);  // 70656 B
    cudaFuncSetAttribute(k_tile128, cudaFuncAttributeMaxDynamicSharedMemorySize,
                         TILE_SMEM);

    k_init<<<1, 256>>>();
    k_rownorm<<<512, 256>>>(x, 0);
    k_rownorm<<<512, 256>>>(y, 1);

    dim3 tg(32, 32, 3);
    k_tile128<<<tg, 256, TILE_SMEM>>>(x, y);   // -> g_xx, g_yy, g_zz

    k_hist0<<<1024, 256>>>();
    k_select<<<1, 64>>>(0, ks);
    k_hist1<<<1024, 256>>>();
    k_select<<<1, 64>>>(1, ks);
    k_hist2<<<1024, 256>>>();
    k_select<<<1, 64>>>(2, ks);                // -> median, scales, fast flag

    dim3 rg(4096, 3);
    k_rowreduce<<<rg, 256>>>();                // stage-A rows for all 3
    k_stageB<<<3, 256>>>();                    // stage-B sums
    k_fin<<<1, 1>>>((float*)d_out);
}

// round 8
// speedup vs baseline: 1.5171x; 1.0120x over previous
#include <cuda_runtime.h>

#define NROW 4096
#define DDIM 64

// ---------------- device scratch (no allocations allowed) ----------------
static __device__ float        g_xx[(long long)NROW * NROW];   // 64 MB dist(x,x)
static __device__ float        g_yy[(long long)NROW * NROW];   // 64 MB dist(y,y)
static __device__ float        g_zz[(long long)NROW * NROW];   // 64 MB dist(x,y)
static __device__ float        g_norms[2][NROW];               // row norms of x, y
static __device__ float        g_rows[3][NROW];                // stage-A f32 row sums
static __device__ float        g_S[3];                         // stage-B f32 sums
static __device__ unsigned int g_h0[2048];
static __device__ unsigned int g_h1[2048];
static __device__ unsigned int g_h2[1024];
static __device__ unsigned int g_pfx0, g_pfx1, g_rank;
static __device__ float        g_par[8];   // [0..4]=s_k, [5]=fast-chain flag

// device-side selector (never pass __device__ symbols from host code)
__device__ __forceinline__ float* mat_of(int slot) {
    return (slot == 0) ? g_xx : (slot == 1) ? g_yy : g_zz;
}

// ---------------- helpers ----------------
// Cephes-style minimax expf (~1 ulp, zero-mean error). Flag-proof: FMA only.
__device__ __forceinline__ float my_exp(float x) {
    x = fmaxf(x, -87.0f);
    float z = floorf(fmaf(x, 1.44269504088896341f, 0.5f));
    float r = fmaf(z, -0.693359375f, x);
    r = fmaf(z, 2.12194440e-4f, r);
    int n = (int)z;
    float p = 1.9875691500e-4f;
    p = fmaf(p, r, 1.3981999507e-3f);
    p = fmaf(p, r, 8.3334519073e-3f);
    p = fmaf(p, r, 4.1665795894e-2f);
    p = fmaf(p, r, 1.6666665459e-1f);
    p = fmaf(p, r, 5.0000001201e-1f);
    float res = fmaf(p, r * r, r) + 1.0f;
    return res * __int_as_float((n + 127) << 23);
}

// exact-replica 5-exp kernel mean: ((((e0+e1)+e2)+e3)+e4) / 5.0f
__device__ __forceinline__ float kmean5(float d, float s0, float s1, float s2,
                                        float s3, float s4) {
    float s = my_exp(d * s0);
    s = s + my_exp(d * s1);
    s = s + my_exp(d * s2);
    s = s + my_exp(d * s3);
    s = s + my_exp(d * s4);
    return s / 5.0f;
}

// fast chain (valid when s_{k+1} == 2*s_k exactly): 2 exps + 3 muls.
__device__ __forceinline__ float kmean5f(float d, float s0) {
    float v  = d * s0;
    float e0 = my_exp(v);
    float e2 = my_exp(4.0f * v);
    float e1 = e0 * e0;      // exp(2v)
    float e3 = e2 * e2;      // exp(8v)
    float e4 = e3 * e3;      // exp(16v)
    float s = e0 + e1;
    s = s + e2;
    s = s + e3;
    s = s + e4;
    return s / 5.0f;
}

// monotone key transform for float radix select
__device__ __forceinline__ unsigned int fkey(float f) {
    unsigned int b = __float_as_uint(f);
    return b ^ ((b & 0x80000000u) ? 0xffffffffu : 0x80000000u);
}

// warp-aggregated shared histogram add
__device__ __forceinline__ void hadd(unsigned int* sh, unsigned int bin) {
    unsigned int m = __match_any_sync(0xffffffffu, bin);
    if ((int)(threadIdx.x & 31u) == (int)(__ffs(m) - 1))
        atomicAdd(&sh[bin], (unsigned int)__popc(m));
}

// ---------------- kernels ----------------
__global__ void k_init() {
    int t = threadIdx.x;
    for (int i = t; i < 2048; i += 256) { g_h0[i] = 0u; g_h1[i] = 0u; }
    for (int i = t; i < 1024; i += 256) g_h2[i] = 0u;
    if (t == 0) {
        g_rank = 8388607u;  // (N*N - 1) / 2 : lower-median rank
        g_pfx0 = 0u; g_pfx1 = 0u;
    }
}

__global__ void k_rownorm(const float* __restrict__ a, int which) {
    int row  = blockIdx.x * 8 + (threadIdx.x >> 5);
    int lane = threadIdx.x & 31;
    float v0 = a[row * DDIM + lane];
    float v1 = a[row * DDIM + 32 + lane];
    float s  = v0 * v0 + v1 * v1;
#pragma unroll
    for (int o = 16; o > 0; o >>= 1) s += __shfl_down_sync(0xffffffffu, s, o);
    if (lane == 0) g_norms[which][row] = s;
}

// 128x128 tile, 256 threads, 8x8 per thread, K=64, grid.z selects matrix.
// Software-pipelined: double-buffered a/b operand registers, LDS for k+1
// issued before the FMAs of k (prefetch of k+2 at k=62 reads padding cols,
// harmless). Per-(r,c) fmaf order over k is unchanged -> bit-exact distances.
__global__ void __launch_bounds__(256, 2) k_tile128(const float* __restrict__ x,
                                                    const float* __restrict__ y) {
    extern __shared__ float sm[];
    float* As = sm;             // [128][69]
    float* Bs = sm + 128 * 69;  // [128][69]

    const int z = blockIdx.z;
    const float* A = (z == 1) ? y : x;
    const float* B = (z == 0) ? x : y;
    const int anw = (z == 1) ? 1 : 0;
    const int bnw = (z == 0) ? 0 : 1;
    float* OUT = mat_of(z);

    const int bm  = blockIdx.y * 128;
    const int bc  = blockIdx.x * 128;
    const int tid = threadIdx.x;

    const float4* Ag = reinterpret_cast<const float4*>(A + (long long)bm * DDIM);
    const float4* Bg = reinterpret_cast<const float4*>(B + (long long)bc * DDIM);
#pragma unroll
    for (int i = tid; i < 2048; i += 256) {
        int row = i >> 4, f4 = i & 15;
        float4 va = Ag[row * 16 + f4];
        float4 vb = Bg[row * 16 + f4];
        int c4 = f4 * 4;
        As[row * 69 + c4 + 0] = va.x; As[row * 69 + c4 + 1] = va.y;
        As[row * 69 + c4 + 2] = va.z; As[row * 69 + c4 + 3] = va.w;
        Bs[row * 69 + c4 + 0] = vb.x; Bs[row * 69 + c4 + 1] = vb.y;
        Bs[row * 69 + c4 + 2] = vb.z; Bs[row * 69 + c4 + 3] = vb.w;
    }
    __syncthreads();

    const int tx = tid & 15, ty = tid >> 4;

    // per-thread smem row bases
    int arow[8], brow[8];
#pragma unroll
    for (int i = 0; i < 8; i++) arow[i] = (ty + 16 * i) * 69;
#pragma unroll
    for (int j = 0; j < 8; j++)
        brow[j] = (2 * tx + 32 * (j >> 1) + (j & 1)) * 69;

    float acc[8][8];
#pragma unroll
    for (int i = 0; i < 8; i++)
#pragma unroll
        for (int j = 0; j < 8; j++) acc[i][j] = 0.0f;

    float a0[8], b0[8], a1[8], b1[8];
#pragma unroll
    for (int i = 0; i < 8; i++) a0[i] = As[arow[i]];
#pragma unroll
    for (int j = 0; j < 8; j++) b0[j] = Bs[brow[j]];

#pragma unroll 4
    for (int k = 0; k < 64; k += 2) {
        // prefetch operands for k+1
#pragma unroll
        for (int i = 0; i < 8; i++) a1[i] = As[arow[i] + k + 1];
#pragma unroll
        for (int j = 0; j < 8; j++) b1[j] = Bs[brow[j] + k + 1];
        // FMAs for k
#pragma unroll
        for (int i = 0; i < 8; i++)
#pragma unroll
            for (int j = 0; j < 8; j++)
                acc[i][j] = fmaf(a0[i], b0[j], acc[i][j]);
        // prefetch operands for k+2 (at k=62 reads padding col 64 — unused)
#pragma unroll
        for (int i = 0; i < 8; i++) a0[i] = As[arow[i] + k + 2];
#pragma unroll
        for (int j = 0; j < 8; j++) b0[j] = Bs[brow[j] + k + 2];
        // FMAs for k+1
#pragma unroll
        for (int i = 0; i < 8; i++)
#pragma unroll
            for (int j = 0; j < 8; j++)
                acc[i][j] = fmaf(a1[i], b1[j], acc[i][j]);
    }

    const float* an = g_norms[anw];
    const float* bn = g_norms[bnw];
#pragma unroll
    for (int i = 0; i < 8; i++) {
        int r = bm + ty + 16 * i;
        float base = an[r];
#pragma unroll
        for (int h = 0; h < 4; h++) {
            int c = bc + 2 * tx + 32 * h;
            float2 o;
            o.x = fmaf(-2.0f, acc[i][2 * h + 0], base + bn[c + 0]);
            o.y = fmaf(-2.0f, acc[i][2 * h + 1], base + bn[c + 1]);
            *reinterpret_cast<float2*>(&OUT[(long long)r * NROW + c]) = o;
        }
    }
}

// ---- 3-pass radix select for exact lower median over g_xx ----
__global__ void k_hist0() {
    __shared__ unsigned int sh[2048];
    for (int i = threadIdx.x; i < 2048; i += 256) sh[i] = 0u;
    __syncthreads();
    const float4* p = reinterpret_cast<const float4*>(g_xx);
    unsigned int i = blockIdx.x * 256u + threadIdx.x;
    const unsigned int stride = 1024u * 256u;
#pragma unroll 2
    for (int it = 0; it < 16; it++, i += stride) {
        float4 v = p[i];
        hadd(sh, fkey(v.x) >> 21);
        hadd(sh, fkey(v.y) >> 21);
        hadd(sh, fkey(v.z) >> 21);
        hadd(sh, fkey(v.w) >> 21);
    }
    __syncthreads();
    for (int i2 = threadIdx.x; i2 < 2048; i2 += 256) {
        unsigned int v = sh[i2];
        if (v) atomicAdd(&g_h0[i2], v);
    }
}

__global__ void k_hist1() {
    __shared__ unsigned int sh[2048];
    for (int i = threadIdx.x; i < 2048; i += 256) sh[i] = 0u;
    __syncthreads();
    const unsigned int pfx = g_pfx0;
    const float4* p = reinterpret_cast<const float4*>(g_xx);
    unsigned int i = blockIdx.x * 256u + threadIdx.x;
    const unsigned int stride = 1024u * 256u;
    for (int it = 0; it < 16; it++, i += stride) {
        float4 v = p[i];
        unsigned int k;
        k = fkey(v.x); if ((k >> 21) == pfx) atomicAdd(&sh[(k >> 10) & 2047u], 1u);
        k = fkey(v.y); if ((k >> 21) == pfx) atomicAdd(&sh[(k >> 10) & 2047u], 1u);
        k = fkey(v.z); if ((k >> 21) == pfx) atomicAdd(&sh[(k >> 10) & 2047u], 1u);
        k = fkey(v.w); if ((k >> 21) == pfx) atomicAdd(&sh[(k >> 10) & 2047u], 1u);
    }
    __syncthreads();
    for (int i2 = threadIdx.x; i2 < 2048; i2 += 256) {
        unsigned int v = sh[i2];
        if (v) atomicAdd(&g_h1[i2], v);
    }
}

__global__ void k_hist2() {
    __shared__ unsigned int sh[1024];
    for (int i = threadIdx.x; i < 1024; i += 256) sh[i] = 0u;
    __syncthreads();
    const unsigned int pfx = g_pfx1;
    const float4* p = reinterpret_cast<const float4*>(g_xx);
    unsigned int i = blockIdx.x * 256u + threadIdx.x;
    const unsigned int stride = 1024u * 256u;
    for (int it = 0; it < 16; it++, i += stride) {
        float4 v = p[i];
        unsigned int k;
        k = fkey(v.x); if ((k >> 10) == pfx) atomicAdd(&sh[k & 1023u], 1u);
        k = fkey(v.y); if ((k >> 10) == pfx) atomicAdd(&sh[k & 1023u], 1u);
        k = fkey(v.z); if ((k >> 10) == pfx) atomicAdd(&sh[k & 1023u], 1u);
        k = fkey(v.w); if ((k >> 10) == pfx) atomicAdd(&sh[k & 1023u], 1u);
    }
    __syncthreads();
    for (int i2 = threadIdx.x; i2 < 1024; i2 += 256) {
        unsigned int v = sh[i2];
        if (v) atomicAdd(&g_h2[i2], v);
    }
}

__global__ void k_select(int pass, const float* __restrict__ ks) {
    __shared__ unsigned int sh[2048];
    __shared__ unsigned int part[64];
    const unsigned int* hist = (pass == 0) ? g_h0 : (pass == 1) ? g_h1 : g_h2;
    const int nbins = (pass == 2) ? 1024 : 2048;
    const int per   = nbins / 64;
    const int tid   = threadIdx.x;  // 64 threads
    unsigned int s = 0;
    for (int i = 0; i < per; i++) {
        unsigned int v = hist[tid * per + i];
        sh[tid * per + i] = v;
        s += v;
    }
    part[tid] = s;
    __syncthreads();
    if (tid == 0) {
        unsigned int rank = g_rank, cum = 0;
        int seg = 0;
        while (seg < 63 && cum + part[seg] <= rank) { cum += part[seg]; seg++; }
        int b = seg * per;
        while (cum + sh[b] <= rank) { cum += sh[b]; b++; }
        g_rank = rank - cum;
        if (pass == 0) {
            g_pfx0 = (unsigned int)b;
        } else if (pass == 1) {
            g_pfx1 = (g_pfx0 << 11) | (unsigned int)b;
        } else {
            unsigned int key  = (g_pfx1 << 10) | (unsigned int)b;
            unsigned int bits = (key & 0x80000000u) ? (key ^ 0x80000000u) : ~key;
            float med  = __uint_as_float(bits);
            float base = -1.0f / med;
            float p0 = base * ks[0], p1 = base * ks[1], p2 = base * ks[2];
            float p3 = base * ks[3], p4 = base * ks[4];
            g_par[0] = p0; g_par[1] = p1; g_par[2] = p2; g_par[3] = p3; g_par[4] = p4;
            bool fast = (p1 == 2.0f * p0) && (p2 == 2.0f * p1) &&
                        (p3 == 2.0f * p2) && (p4 == 2.0f * p3);
            g_par[5] = fast ? 1.0f : 0.0f;
        }
    }
}

// Stage-A XLA row-reduction replica (bit-exact shape). grid=(4096, 3).
__global__ void __launch_bounds__(256) k_rowreduce() {
    __shared__ float ws[8];
    const int r    = blockIdx.x;
    const int slot = blockIdx.y;
    const int diagskip = (slot != 2) ? 1 : 0;
    const int t = threadIdx.x;
    float s0 = g_par[0], s1 = g_par[1], s2 = g_par[2], s3 = g_par[3], s4 = g_par[4];
    const bool fast = g_par[5] > 0.5f;
    const float* M = mat_of(slot);
    const float2* p = reinterpret_cast<const float2*>(M + (long long)r * NROW);

    float ax = 0.0f, ay = 0.0f;
    if (fast) {
#pragma unroll
        for (int i = 0; i < 8; i++) {
            float2 v = p[i * 256 + t];
            int c = (i * 256 + t) * 2;
            float kx = kmean5f(v.x, s0);
            float ky = kmean5f(v.y, s0);
            if (diagskip && c == r)     kx = 0.0f;
            if (diagskip && c + 1 == r) ky = 0.0f;
            ax += kx;
            ay += ky;
        }
    } else {
#pragma unroll
        for (int i = 0; i < 8; i++) {
            float2 v = p[i * 256 + t];
            int c = (i * 256 + t) * 2;
            float kx = (diagskip && c == r)     ? 0.0f : kmean5(v.x, s0, s1, s2, s3, s4);
            float ky = (diagskip && c + 1 == r) ? 0.0f : kmean5(v.y, s0, s1, s2, s3, s4);
            ax += kx;
            ay += ky;
        }
    }
    float v = ax + ay;
#pragma unroll
    for (int o = 16; o > 0; o >>= 1) v += __shfl_down_sync(0xffffffffu, v, o);
    if ((t & 31) == 0) ws[t >> 5] = v;
    __syncthreads();
    if (t < 32) {
        float w = (t < 8) ? ws[t] : 0.0f;
#pragma unroll
        for (int o = 16; o > 0; o >>= 1) w += __shfl_down_sync(0xffffffffu, w, o);
        if (t == 0) g_rows[slot][r] = w;
    }
}

// Stage-B: same reduce shape over the 4096 f32 row sums. grid=3.
__global__ void __launch_bounds__(256) k_stageB() {
    __shared__ float ws[8];
    const int slot = blockIdx.x;
    const int t = threadIdx.x;
    const float2* p = reinterpret_cast<const float2*>(g_rows[slot]);
    float ax = 0.0f, ay = 0.0f;
#pragma unroll
    for (int i = 0; i < 8; i++) {
        float2 v = p[i * 256 + t];
        ax += v.x;
        ay += v.y;
    }
    float v = ax + ay;
#pragma unroll
    for (int o = 16; o > 0; o >>= 1) v += __shfl_down_sync(0xffffffffu, v, o);
    if ((t & 31) == 0) ws[t >> 5] = v;
    __syncthreads();
    if (t < 32) {
        float w = (t < 8) ? ws[t] : 0.0f;
#pragma unroll
        for (int o = 16; o > 0; o >>= 1) w += __shfl_down_sync(0xffffffffu, w, o);
        if (t == 0) g_S[slot] = w;
    }
}

// Final combine replicating the reference's f32 arithmetic.
__global__ void k_fin(float* out) {
    float S1 = g_S[0], S2 = g_S[1], S3 = g_S[2];
    float od = (float)(1.0 / 16773120.0);        // 1/(4096*4095) in f32
    float t1 = od * S1;
    float t2 = od * S2;
    float m3 = S3 * (1.0f / 16777216.0f);        // exact power-of-two scale
    float t3 = 2.0f * m3;                        // exact
    out[0] = (t1 + t2) - t3;
}

// ---------------- entry ----------------
extern "C" void kernel_launch(void* const* d_in, const int* in_sizes, int n_in,
                              void* d_out, int out_size) {
    (void)in_sizes; (void)n_in; (void)out_size;
    const float* x  = (const float*)d_in[0];
    const float* y  = (const float*)d_in[1];
    const float* ks = (const float*)d_in[2];

    const int TILE_SMEM = 2 * 128 * 69 * (int)sizeof(float);  // 70656 B
    cudaFuncSetAttribute(k_tile128, cudaFuncAttributeMaxDynamicSharedMemorySize,
                         TILE_SMEM);

    k_init<<<1, 256>>>();
    k_rownorm<<<512, 256>>>(x, 0);
    k_rownorm<<<512, 256>>>(y, 1);

    dim3 tg(32, 32, 3);
    k_tile128<<<tg, 256, TILE_SMEM>>>(x, y);   // -> g_xx, g_yy, g_zz

    k_hist0<<<1024, 256>>>();
    k_select<<<1, 64>>>(0, ks);
    k_hist1<<<1024, 256>>>();
    k_select<<<1, 64>>>(1, ks);
    k_hist2<<<1024, 256>>>();
    k_select<<<1, 64>>>(2, ks);                // -> median, scales, fast flag

    dim3 rg(4096, 3);
    k_rowreduce<<<rg, 256>>>();                // stage-A rows for all 3
    k_stageB<<<3, 256>>>();                    // stage-B sums
    k_fin<<<1, 1>>>((float*)d_out);
}

// round 9
// speedup vs baseline: 1.6621x; 1.0956x over previous
#include <cuda_runtime.h>
#include <math.h>

#define NROW 4096
#define DDIM 64

// ---------------- device scratch (no allocations allowed) ----------------
static __device__ float        g_xx[(long long)NROW * NROW];   // 64 MB dist(x,x)
static __device__ float        g_yy[(long long)NROW * NROW];   // 64 MB dist(y,y)
static __device__ float        g_zz[(long long)NROW * NROW];   // 64 MB dist(x,y)
static __device__ float        g_norms[2][NROW];               // row norms of x, y
static __device__ float        g_rows[3][NROW];                // stage-A f32 row sums
static __device__ float        g_S[3];                         // stage-B f32 sums
static __device__ unsigned int g_h0[2048];
static __device__ unsigned int g_h1[2048];
static __device__ unsigned int g_h2[1024];
static __device__ unsigned int g_pfx0, g_pfx1, g_rank;
static __device__ float        g_par[8];   // [0..4]=s_k, [5]=fast-chain flag

// device-side selector (never pass __device__ symbols from host code)
__device__ __forceinline__ float* mat_of(int slot) {
    return (slot == 0) ? g_xx : (slot == 1) ? g_yy : g_zz;
}

// ---------------- helpers ----------------
// Cephes-style minimax expf (~1 ulp). Matches the reference's XLA exp closely
// enough that S-sum rounding bins are unaffected (proven: rel_err == 0.0).
__device__ __forceinline__ float my_exp(float x) {
    x = fmaxf(x, -87.0f);
    float z = floorf(fmaf(x, 1.44269504088896341f, 0.5f));
    float r = fmaf(z, -0.693359375f, x);
    r = fmaf(z, 2.12194440e-4f, r);
    int n = (int)z;
    float p = 1.9875691500e-4f;
    p = fmaf(p, r, 1.3981999507e-3f);
    p = fmaf(p, r, 8.3334519073e-3f);
    p = fmaf(p, r, 4.1665795894e-2f);
    p = fmaf(p, r, 1.6666665459e-1f);
    p = fmaf(p, r, 5.0000001201e-1f);
    float res = fmaf(p, r * r, r) + 1.0f;
    return res * __int_as_float((n + 127) << 23);
}

// exact-replica 5-exp kernel mean: ((((e0+e1)+e2)+e3)+e4) / 5.0f
__device__ __forceinline__ float kmean5(float d, float s0, float s1, float s2,
                                        float s3, float s4) {
    float s = my_exp(d * s0);
    s = s + my_exp(d * s1);
    s = s + my_exp(d * s2);
    s = s + my_exp(d * s3);
    s = s + my_exp(d * s4);
    return s / 5.0f;
}

// fast chain (valid when s_{k+1} == 2*s_k exactly): 2 exps + 3 muls.
__device__ __forceinline__ float kmean5f(float d, float s0) {
    float v  = d * s0;
    float e0 = my_exp(v);
    float e2 = my_exp(4.0f * v);
    float e1 = e0 * e0;      // exp(2v)
    float e3 = e2 * e2;      // exp(8v)
    float e4 = e3 * e3;      // exp(16v)
    float s = e0 + e1;
    s = s + e2;
    s = s + e3;
    s = s + e4;
    return s / 5.0f;
}

// monotone key transform for float radix select
__device__ __forceinline__ unsigned int fkey(float f) {
    unsigned int b = __float_as_uint(f);
    return b ^ ((b & 0x80000000u) ? 0xffffffffu : 0x80000000u);
}

// warp-aggregated shared histogram add
__device__ __forceinline__ void hadd(unsigned int* sh, unsigned int bin) {
    unsigned int m = __match_any_sync(0xffffffffu, bin);
    if ((int)(threadIdx.x & 31u) == (int)(__ffs(m) - 1))
        atomicAdd(&sh[bin], (unsigned int)__popc(m));
}

// ---------------- kernels ----------------
__global__ void k_init() {
    int t = threadIdx.x;
    for (int i = t; i < 2048; i += 256) { g_h0[i] = 0u; g_h1[i] = 0u; }
    for (int i = t; i < 1024; i += 256) g_h2[i] = 0u;
    if (t == 0) {
        g_rank = 8388607u;  // (N*N - 1) / 2 : lower-median rank
        g_pfx0 = 0u; g_pfx1 = 0u;
    }
}

__global__ void k_rownorm(const float* __restrict__ a, int which) {
    int row  = blockIdx.x * 8 + (threadIdx.x >> 5);
    int lane = threadIdx.x & 31;
    float v0 = a[row * DDIM + lane];
    float v1 = a[row * DDIM + 32 + lane];
    float s  = v0 * v0 + v1 * v1;
#pragma unroll
    for (int o = 16; o > 0; o >>= 1) s += __shfl_down_sync(0xffffffffu, s, o);
    if (lane == 0) g_norms[which][row] = s;
}

// 128x128 tile, 256 threads, 8x8/thread, K=64. SYMMETRY-AWARE:
// xx and yy compute only upper-triangle blocks (by >= bx) and mirror
// off-diagonal blocks via a transposed smem staging store. The mirror is
// BIT-EXACT: fmaf multiply commutes, and the epilogue base norm[r]+norm[c]
// commutes because an==bn for symmetric matrices.
// Linear grid: [0,528)=xx tri, [528,1056)=yy tri, [1056,2080)=zz full.
__global__ void __launch_bounds__(256, 2) k_tile128(const float* __restrict__ x,
                                                    const float* __restrict__ y) {
    extern __shared__ float sm[];
    float* As = sm;             // [128][69]
    float* Bs = sm + 128 * 69;  // [128][69]

    int idx = blockIdx.x;
    int z, bxb, byb;
    if (idx < 1056) {
        z = (idx < 528) ? 0 : 1;
        int t = idx - z * 528;
        int by = (int)((sqrtf(8.0f * (float)t + 1.0f) - 1.0f) * 0.5f);
        while (by * (by + 1) / 2 > t) by--;
        while ((by + 1) * (by + 2) / 2 <= t) by++;
        byb = by;
        bxb = t - by * (by + 1) / 2;     // bxb <= byb
    } else {
        z = 2;
        int t = idx - 1056;
        bxb = t & 31;
        byb = t >> 5;
    }

    const float* A = (z == 1) ? y : x;
    const float* B = (z == 0) ? x : y;
    const int anw = (z == 1) ? 1 : 0;
    const int bnw = (z == 0) ? 0 : 1;
    float* OUT = mat_of(z);

    const int bm  = byb * 128;
    const int bc  = bxb * 128;
    const int tid = threadIdx.x;

    const float4* Ag = reinterpret_cast<const float4*>(A + (long long)bm * DDIM);
    const float4* Bg = reinterpret_cast<const float4*>(B + (long long)bc * DDIM);
#pragma unroll
    for (int i = tid; i < 2048; i += 256) {
        int row = i >> 4, f4 = i & 15;
        float4 va = Ag[row * 16 + f4];
        float4 vb = Bg[row * 16 + f4];
        int c4 = f4 * 4;
        As[row * 69 + c4 + 0] = va.x; As[row * 69 + c4 + 1] = va.y;
        As[row * 69 + c4 + 2] = va.z; As[row * 69 + c4 + 3] = va.w;
        Bs[row * 69 + c4 + 0] = vb.x; Bs[row * 69 + c4 + 1] = vb.y;
        Bs[row * 69 + c4 + 2] = vb.z; Bs[row * 69 + c4 + 3] = vb.w;
    }
    __syncthreads();

    const int tx = tid & 15, ty = tid >> 4;

    int arow[8], brow[8];
#pragma unroll
    for (int i = 0; i < 8; i++) arow[i] = (ty + 16 * i) * 69;
#pragma unroll
    for (int j = 0; j < 8; j++)
        brow[j] = (2 * tx + 32 * (j >> 1) + (j & 1)) * 69;

    float acc[8][8];
#pragma unroll
    for (int i = 0; i < 8; i++)
#pragma unroll
        for (int j = 0; j < 8; j++) acc[i][j] = 0.0f;

    float a0[8], b0[8], a1[8], b1[8];
#pragma unroll
    for (int i = 0; i < 8; i++) a0[i] = As[arow[i]];
#pragma unroll
    for (int j = 0; j < 8; j++) b0[j] = Bs[brow[j]];

#pragma unroll 4
    for (int k = 0; k < 64; k += 2) {
#pragma unroll
        for (int i = 0; i < 8; i++) a1[i] = As[arow[i] + k + 1];
#pragma unroll
        for (int j = 0; j < 8; j++) b1[j] = Bs[brow[j] + k + 1];
#pragma unroll
        for (int i = 0; i < 8; i++)
#pragma unroll
            for (int j = 0; j < 8; j++)
                acc[i][j] = fmaf(a0[i], b0[j], acc[i][j]);
#pragma unroll
        for (int i = 0; i < 8; i++) a0[i] = As[arow[i] + k + 2];  // k=62 -> pad col, unused
#pragma unroll
        for (int j = 0; j < 8; j++) b0[j] = Bs[brow[j] + k + 2];
#pragma unroll
        for (int i = 0; i < 8; i++)
#pragma unroll
            for (int j = 0; j < 8; j++)
                acc[i][j] = fmaf(a1[i], b1[j], acc[i][j]);
    }

    const float* an = g_norms[anw];
    const float* bn = g_norms[bnw];
    const bool mirror = (z < 2) && (bm != bc);
    float* T = sm;  // transposed staging [128][129] — reuses As/Bs space

    if (mirror) __syncthreads();   // all k-loop smem reads complete before overwrite

#pragma unroll
    for (int i = 0; i < 8; i++) {
        int rl = ty + 16 * i;
        int r  = bm + rl;
        float base = an[r];
#pragma unroll
        for (int h = 0; h < 4; h++) {
            int cl = 2 * tx + 32 * h;
            int c  = bc + cl;
            float2 o;
            o.x = fmaf(-2.0f, acc[i][2 * h + 0], base + bn[c + 0]);
            o.y = fmaf(-2.0f, acc[i][2 * h + 1], base + bn[c + 1]);
            *reinterpret_cast<float2*>(&OUT[(long long)r * NROW + c]) = o;
            if (mirror) {
                T[(cl + 0) * 129 + rl] = o.x;   // conflict-free: bank=2tx+ty(+1)
                T[(cl + 1) * 129 + rl] = o.y;
            }
        }
    }

    if (mirror) {
        __syncthreads();
        // write transposed block: rows of T (= columns of original) coalesced.
        // thread handles row rr = tid>>1, 64 cols at base (tid&1)*64.
        int rr   = tid >> 1;
        int cb   = (tid & 1) * 64;
        long long obase = (long long)(bc + rr) * NROW + bm + cb;
#pragma unroll
        for (int v = 0; v < 16; v++) {
            float4 o;
            o.x = T[rr * 129 + cb + 4 * v + 0];
            o.y = T[rr * 129 + cb + 4 * v + 1];
            o.z = T[rr * 129 + cb + 4 * v + 2];
            o.w = T[rr * 129 + cb + 4 * v + 3];
            *reinterpret_cast<float4*>(&OUT[obase + 4 * v]) = o;
        }
    }
}

// ---- 3-pass radix select for exact lower median over g_xx ----
__global__ void k_hist0() {
    __shared__ unsigned int sh[2048];
    for (int i = threadIdx.x; i < 2048; i += 256) sh[i] = 0u;
    __syncthreads();
    const float4* p = reinterpret_cast<const float4*>(g_xx);
    unsigned int i = blockIdx.x * 256u + threadIdx.x;
    const unsigned int stride = 1024u * 256u;
#pragma unroll 2
    for (int it = 0; it < 16; it++, i += stride) {
        float4 v = p[i];
        hadd(sh, fkey(v.x) >> 21);
        hadd(sh, fkey(v.y) >> 21);
        hadd(sh, fkey(v.z) >> 21);
        hadd(sh, fkey(v.w) >> 21);
    }
    __syncthreads();
    for (int i2 = threadIdx.x; i2 < 2048; i2 += 256) {
        unsigned int v = sh[i2];
        if (v) atomicAdd(&g_h0[i2], v);
    }
}

__global__ void k_hist1() {
    __shared__ unsigned int sh[2048];
    for (int i = threadIdx.x; i < 2048; i += 256) sh[i] = 0u;
    __syncthreads();
    const unsigned int pfx = g_pfx0;
    const float4* p = reinterpret_cast<const float4*>(g_xx);
    unsigned int i = blockIdx.x * 256u + threadIdx.x;
    const unsigned int stride = 1024u * 256u;
    for (int it = 0; it < 16; it++, i += stride) {
        float4 v = p[i];
        unsigned int k;
        k = fkey(v.x); if ((k >> 21) == pfx) atomicAdd(&sh[(k >> 10) & 2047u], 1u);
        k = fkey(v.y); if ((k >> 21) == pfx) atomicAdd(&sh[(k >> 10) & 2047u], 1u);
        k = fkey(v.z); if ((k >> 21) == pfx) atomicAdd(&sh[(k >> 10) & 2047u], 1u);
        k = fkey(v.w); if ((k >> 21) == pfx) atomicAdd(&sh[(k >> 10) & 2047u], 1u);
    }
    __syncthreads();
    for (int i2 = threadIdx.x; i2 < 2048; i2 += 256) {
        unsigned int v = sh[i2];
        if (v) atomicAdd(&g_h1[i2], v);
    }
}

__global__ void k_hist2() {
    __shared__ unsigned int sh[1024];
    for (int i = threadIdx.x; i < 1024; i += 256) sh[i] = 0u;
    __syncthreads();
    const unsigned int pfx = g_pfx1;
    const float4* p = reinterpret_cast<const float4*>(g_xx);
    unsigned int i = blockIdx.x * 256u + threadIdx.x;
    const unsigned int stride = 1024u * 256u;
    for (int it = 0; it < 16; it++, i += stride) {
        float4 v = p[i];
        unsigned int k;
        k = fkey(v.x); if ((k >> 10) == pfx) atomicAdd(&sh[k & 1023u], 1u);
        k = fkey(v.y); if ((k >> 10) == pfx) atomicAdd(&sh[k & 1023u], 1u);
        k = fkey(v.z); if ((k >> 10) == pfx) atomicAdd(&sh[k & 1023u], 1u);
        k = fkey(v.w); if ((k >> 10) == pfx) atomicAdd(&sh[k & 1023u], 1u);
    }
    __syncthreads();
    for (int i2 = threadIdx.x; i2 < 1024; i2 += 256) {
        unsigned int v = sh[i2];
        if (v) atomicAdd(&g_h2[i2], v);
    }
}

__global__ void k_select(int pass, const float* __restrict__ ks) {
    __shared__ unsigned int sh[2048];
    __shared__ unsigned int part[64];
    const unsigned int* hist = (pass == 0) ? g_h0 : (pass == 1) ? g_h1 : g_h2;
    const int nbins = (pass == 2) ? 1024 : 2048;
    const int per   = nbins / 64;
    const int tid   = threadIdx.x;  // 64 threads
    unsigned int s = 0;
    for (int i = 0; i < per; i++) {
        unsigned int v = hist[tid * per + i];
        sh[tid * per + i] = v;
        s += v;
    }
    part[tid] = s;
    __syncthreads();
    if (tid == 0) {
        unsigned int rank = g_rank, cum = 0;
        int seg = 0;
        while (seg < 63 && cum + part[seg] <= rank) { cum += part[seg]; seg++; }
        int b = seg * per;
        while (cum + sh[b] <= rank) { cum += sh[b]; b++; }
        g_rank = rank - cum;
        if (pass == 0) {
            g_pfx0 = (unsigned int)b;
        } else if (pass == 1) {
            g_pfx1 = (g_pfx0 << 11) | (unsigned int)b;
        } else {
            unsigned int key  = (g_pfx1 << 10) | (unsigned int)b;
            unsigned int bits = (key & 0x80000000u) ? (key ^ 0x80000000u) : ~key;
            float med  = __uint_as_float(bits);
            float base = -1.0f / med;
            float p0 = base * ks[0], p1 = base * ks[1], p2 = base * ks[2];
            float p3 = base * ks[3], p4 = base * ks[4];
            g_par[0] = p0; g_par[1] = p1; g_par[2] = p2; g_par[3] = p3; g_par[4] = p4;
            bool fast = (p1 == 2.0f * p0) && (p2 == 2.0f * p1) &&
                        (p3 == 2.0f * p2) && (p4 == 2.0f * p3);
            g_par[5] = fast ? 1.0f : 0.0f;
        }
    }
}

// Stage-A XLA row-reduction replica (bit-exact shape). grid=(4096, 3).
__global__ void __launch_bounds__(256) k_rowreduce() {
    __shared__ float ws[8];
    const int r    = blockIdx.x;
    const int slot = blockIdx.y;
    const int diagskip = (slot != 2) ? 1 : 0;
    const int t = threadIdx.x;
    float s0 = g_par[0], s1 = g_par[1], s2 = g_par[2], s3 = g_par[3], s4 = g_par[4];
    const bool fast = g_par[5] > 0.5f;
    const float* M = mat_of(slot);
    const float2* p = reinterpret_cast<const float2*>(M + (long long)r * NROW);

    float ax = 0.0f, ay = 0.0f;
    if (fast) {
#pragma unroll
        for (int i = 0; i < 8; i++) {
            float2 v = p[i * 256 + t];
            int c = (i * 256 + t) * 2;
            float kx = kmean5f(v.x, s0);
            float ky = kmean5f(v.y, s0);
            if (diagskip && c == r)     kx = 0.0f;
            if (diagskip && c + 1 == r) ky = 0.0f;
            ax += kx;
            ay += ky;
        }
    } else {
#pragma unroll
        for (int i = 0; i < 8; i++) {
            float2 v = p[i * 256 + t];
            int c = (i * 256 + t) * 2;
            float kx = (diagskip && c == r)     ? 0.0f : kmean5(v.x, s0, s1, s2, s3, s4);
            float ky = (diagskip && c + 1 == r) ? 0.0f : kmean5(v.y, s0, s1, s2, s3, s4);
            ax += kx;
            ay += ky;
        }
    }
    float v = ax + ay;
#pragma unroll
    for (int o = 16; o > 0; o >>= 1) v += __shfl_down_sync(0xffffffffu, v, o);
    if ((t & 31) == 0) ws[t >> 5] = v;
    __syncthreads();
    if (t < 32) {
        float w = (t < 8) ? ws[t] : 0.0f;
#pragma unroll
        for (int o = 16; o > 0; o >>= 1) w += __shfl_down_sync(0xffffffffu, w, o);
        if (t == 0) g_rows[slot][r] = w;
    }
}

// Stage-B: same reduce shape over the 4096 f32 row sums. grid=3.
__global__ void __launch_bounds__(256) k_stageB() {
    __shared__ float ws[8];
    const int slot = blockIdx.x;
    const int t = threadIdx.x;
    const float2* p = reinterpret_cast<const float2*>(g_rows[slot]);
    float ax = 0.0f, ay = 0.0f;
#pragma unroll
    for (int i = 0; i < 8; i++) {
        float2 v = p[i * 256 + t];
        ax += v.x;
        ay += v.y;
    }
    float v = ax + ay;
#pragma unroll
    for (int o = 16; o > 0; o >>= 1) v += __shfl_down_sync(0xffffffffu, v, o);
    if ((t & 31) == 0) ws[t >> 5] = v;
    __syncthreads();
    if (t < 32) {
        float w = (t < 8) ? ws[t] : 0.0f;
#pragma unroll
        for (int o = 16; o > 0; o >>= 1) w += __shfl_down_sync(0xffffffffu, w, o);
        if (t == 0) g_S[slot] = w;
    }
}

// Final combine replicating the reference's f32 arithmetic.
__global__ void k_fin(float* out) {
    float S1 = g_S[0], S2 = g_S[1], S3 = g_S[2];
    float od = (float)(1.0 / 16773120.0);        // 1/(4096*4095) in f32
    float t1 = od * S1;
    float t2 = od * S2;
    float m3 = S3 * (1.0f / 16777216.0f);        // exact power-of-two scale
    float t3 = 2.0f * m3;                        // exact
    out[0] = (t1 + t2) - t3;
}

// ---------------- entry ----------------
extern "C" void kernel_launch(void* const* d_in, const int* in_sizes, int n_in,
                              void* d_out, int out_size) {
    (void)in_sizes; (void)n_in; (void)out_size;
    const float* x  = (const float*)d_in[0];
    const float* y  = (const float*)d_in[1];
    const float* ks = (const float*)d_in[2];

    const int TILE_SMEM = 2 * 128 * 69 * (int)sizeof(float);  // 70656 B
    cudaFuncSetAttribute(k_tile128, cudaFuncAttributeMaxDynamicSharedMemorySize,
                         TILE_SMEM);

    k_init<<<1, 256>>>();
    k_rownorm<<<512, 256>>>(x, 0);
    k_rownorm<<<512, 256>>>(y, 1);

    // 528 (xx triangle) + 528 (yy triangle) + 1024 (zz full) = 2080 blocks
    k_tile128<<<2080, 256, TILE_SMEM>>>(x, y);

    k_hist0<<<1024, 256>>>();
    k_select<<<1, 64>>>(0, ks);
    k_hist1<<<1024, 256>>>();
    k_select<<<1, 64>>>(1, ks);
    k_hist2<<<1024, 256>>>();
    k_select<<<1, 64>>>(2, ks);                // -> median, scales, fast flag

    dim3 rg(4096, 3);
    k_rowreduce<<<rg, 256>>>();                // stage-A rows for all 3
    k_stageB<<<3, 256>>>();                    // stage-B sums
    k_fin<<<1, 1>>>((float*)d_out);
}